// round 12
// baseline (speedup 1.0000x reference)
#include <cuda_runtime.h>
#include <cuda_fp16.h>
#include <math.h>
#include <stdint.h>

// Problem constants
#define B_  4
#define T_  2048
#define D_  1024
#define H_  16
#define DH_ 64
#define ROWS_ (B_*T_)              // 8192
#define ELEMS_ ((size_t)ROWS_*D_)  // 8,388,608
#define QKVN_ 3072                 // fused QKV width

// Scratch (device globals — no allocation)
__device__ __half g_xh[ELEMS_];                    // fp16 x            [M][1024]
__device__ __half g_wqkvh[(size_t)QKVN_*D_];       // fp16 [Wq|Wk|Wv]^T [3072][1024]
__device__ __half g_woh[(size_t)D_*D_];            // fp16 Wo^T         [1024][1024]
__device__ __half g_qh[ELEMS_];                    // fp16 Q (roped, *1/8) [M][1024]
__device__ __half g_kh[ELEMS_];                    // fp16 K (roped)       [M][1024]
__device__ __half g_vh[ELEMS_];                    // fp16 V^T   [B*H][64 dh][2048 t]
__device__ __half g_ah[ELEMS_];                    // fp16 attn out     [M][1024]

// ---------------------------------------------------------------------------
// Helpers
// ---------------------------------------------------------------------------
__device__ __forceinline__ void mma_f16(float c[4],
                                        uint32_t a0, uint32_t a1, uint32_t a2, uint32_t a3,
                                        uint32_t b0, uint32_t b1)
{
    asm volatile(
        "mma.sync.aligned.m16n8k16.row.col.f32.f16.f16.f32 "
        "{%0,%1,%2,%3}, {%4,%5,%6,%7}, {%8,%9}, {%0,%1,%2,%3};"
        : "+f"(c[0]), "+f"(c[1]), "+f"(c[2]), "+f"(c[3])
        : "r"(a0), "r"(a1), "r"(a2), "r"(a3), "r"(b0), "r"(b1));
}
__device__ __forceinline__ void cp16(void* s, const void* g) {
    uint32_t sa = (uint32_t)__cvta_generic_to_shared(s);
    asm volatile("cp.async.cg.shared.global [%0], [%1], 16;" :: "r"(sa), "l"(g));
}
#define CP_COMMIT() asm volatile("cp.async.commit_group;")
#define CP_WAIT(n)  asm volatile("cp.async.wait_group %0;" :: "n"(n))
__device__ __forceinline__ uint32_t ld32(const __half* p) {
    return *reinterpret_cast<const uint32_t*>(p);
}
__device__ __forceinline__ void st_h2(__half* p, float a, float b) {
    __half2 h = __floats2half2_rn(a, b);
    *(uint32_t*)p = *(uint32_t*)&h;
}

// ---------------------------------------------------------------------------
// Prep kernels
// ---------------------------------------------------------------------------
__global__ __launch_bounds__(256) void cvt_h(const float* __restrict__ src,
                                             __half* __restrict__ dst, int n4)
{
    int i = blockIdx.x * 256 + threadIdx.x;
    if (i >= n4) return;
    float4 v = ((const float4*)src)[i];
    __half2 h0 = __floats2half2_rn(v.x, v.y);
    __half2 h1 = __floats2half2_rn(v.z, v.w);
    *(uint2*)&dst[(size_t)i * 4] = make_uint2(*(uint32_t*)&h0, *(uint32_t*)&h1);
}

// W [k][n] fp32 -> out[(off+n)][k] fp16 (transpose + convert)
__global__ void packwT_h(const float* __restrict__ W, __half* __restrict__ out, int off)
{
    __shared__ float t[32][33];
    int n0 = blockIdx.x * 32, k0 = blockIdx.y * 32;
    int tx = threadIdx.x, ty = threadIdx.y;   // 32 x 8
    #pragma unroll
    for (int i = 0; i < 4; i++)
        t[ty + 8*i][tx] = W[(size_t)(k0 + ty + 8*i) * D_ + n0 + tx];
    __syncthreads();
    #pragma unroll
    for (int i = 0; i < 4; i++) {
        int n = n0 + ty + 8*i;
        out[(size_t)(off + n) * D_ + k0 + tx] = __float2half_rn(t[tx][ty + 8*i]);
    }
}

// ---------------------------------------------------------------------------
// GEMM common config: block tile 128x128, BK=64, 256 threads, warp tile 32x64.
// ---------------------------------------------------------------------------
#define GSTRIDE 72
#define GSTAGE_H (128*GSTRIDE*2)           // fp16 count per stage (A+B)
#define GSMEM (2 * GSTAGE_H * 2)           // bytes: 73728

// Mainloop macro body shared by both GEMMs (A[M,K]@B[N,K]^T, fp32 acc)
#define GEMM_MAINLOOP(A, Bw, K)                                                  \
    float acc[2][8][4];                                                          \
    _Pragma("unroll")                                                            \
    for (int mi = 0; mi < 2; mi++)                                               \
        _Pragma("unroll")                                                        \
        for (int ni = 0; ni < 8; ni++)                                           \
            _Pragma("unroll")                                                    \
            for (int e = 0; e < 4; e++) acc[mi][ni][e] = 0.f;                    \
    auto load_stage = [&](int s, int k0) {                                       \
        __half* As = hsm + s * GSTAGE_H;                                         \
        __half* Bs = As + 128 * GSTRIDE;                                         \
        const __half* Ag = (A) + (size_t)row0 * (K) + k0;                        \
        const __half* Bg = (Bw) + (size_t)col0 * (K) + k0;                       \
        _Pragma("unroll")                                                        \
        for (int i = 0; i < 4; i++) {                                            \
            int idx = tid + i * 256;                                             \
            int r = idx >> 3, seg = idx & 7;                                     \
            cp16(As + r * GSTRIDE + seg * 8, Ag + (size_t)r * (K) + seg * 8);    \
            cp16(Bs + r * GSTRIDE + seg * 8, Bg + (size_t)r * (K) + seg * 8);    \
        }                                                                        \
        CP_COMMIT();                                                             \
    };                                                                           \
    const int NIT = (K) >> 6;                                                    \
    load_stage(0, 0);                                                            \
    for (int it = 0; it < NIT; ++it) {                                           \
        if (it + 1 < NIT) { load_stage((it + 1) & 1, (it + 1) << 6); CP_WAIT(1);}\
        else              { CP_WAIT(0); }                                        \
        __syncthreads();                                                         \
        const __half* As = hsm + (it & 1) * GSTAGE_H;                            \
        const __half* Bs = As + 128 * GSTRIDE;                                   \
        _Pragma("unroll")                                                        \
        for (int ks = 0; ks < 4; ks++) {                                         \
            const int kk = 16 * ks;                                              \
            uint32_t bf[8][2];                                                   \
            _Pragma("unroll")                                                    \
            for (int ni = 0; ni < 8; ni++) {                                     \
                int cb = warp_n * 64 + ni * 8 + grp;                             \
                bf[ni][0] = ld32(Bs + cb * GSTRIDE + kk + 2*tq);                 \
                bf[ni][1] = ld32(Bs + cb * GSTRIDE + kk + 2*tq + 8);             \
            }                                                                    \
            _Pragma("unroll")                                                    \
            for (int mi = 0; mi < 2; mi++) {                                     \
                int rb = warp_m * 32 + mi * 16;                                  \
                uint32_t a0 = ld32(As + (rb + grp)     * GSTRIDE + kk + 2*tq);   \
                uint32_t a1 = ld32(As + (rb + grp + 8) * GSTRIDE + kk + 2*tq);   \
                uint32_t a2 = ld32(As + (rb + grp)     * GSTRIDE + kk + 2*tq+8); \
                uint32_t a3 = ld32(As + (rb + grp + 8) * GSTRIDE + kk + 2*tq+8); \
                _Pragma("unroll")                                                \
                for (int ni = 0; ni < 8; ni++)                                   \
                    mma_f16(acc[mi][ni], a0, a1, a2, a3, bf[ni][0], bf[ni][1]);  \
            }                                                                    \
        }                                                                        \
        __syncthreads();                                                         \
    }

// ---------------------------------------------------------------------------
// Fused QKV GEMM: C = xh @ wqkv^T with epilogue applying RoPE (+1/8 scale on Q),
// fp16 conversion, and V transpose to [bh][dh][T]. No fp32 intermediate.
// ---------------------------------------------------------------------------
__global__ __launch_bounds__(256) void gemm_qkv(const __half* __restrict__ A,
                                                const __half* __restrict__ Bw,
                                                __half* __restrict__ Qh,
                                                __half* __restrict__ Kh,
                                                __half* __restrict__ Vh,
                                                const float* __restrict__ cosp,
                                                const float* __restrict__ sinp)
{
    extern __shared__ __half hsm[];
    const int tid  = threadIdx.x;
    const int lane = tid & 31;
    const int warp = tid >> 5;
    const int warp_m = warp & 3;
    const int warp_n = warp >> 2;
    const int grp = lane >> 2;
    const int tq  = lane & 3;
    const int row0 = blockIdx.y * 128;
    const int col0 = blockIdx.x * 128;

    GEMM_MAINLOOP(A, Bw, D_)

    const int sector = col0 >> 10;          // 0=Q, 1=K, 2=V
    if (sector < 2) {
        __half* dst = (sector == 0) ? Qh : Kh;
        const float sc = (sector == 0) ? 0.125f : 1.0f;
        const int cbase = (col0 & 1023) + warp_n * 64;   // head-local col base
        #pragma unroll
        for (int mi = 0; mi < 2; mi++) {
            int r0 = row0 + warp_m * 32 + mi * 16 + grp;
            int r1 = r0 + 8;
            int t0 = r0 & (T_ - 1), t1 = r1 & (T_ - 1);
            #pragma unroll
            for (int ni = 0; ni < 4; ni++) {
                int i = ni * 8 + 2 * tq;    // 0..30 (lo half of head)
                float2 c0l = *(const float2*)&cosp[t0 * DH_ + i];
                float2 s0l = *(const float2*)&sinp[t0 * DH_ + i];
                float2 c0h = *(const float2*)&cosp[t0 * DH_ + i + 32];
                float2 s0h = *(const float2*)&sinp[t0 * DH_ + i + 32];
                float2 c1l = *(const float2*)&cosp[t1 * DH_ + i];
                float2 s1l = *(const float2*)&sinp[t1 * DH_ + i];
                float2 c1h = *(const float2*)&cosp[t1 * DH_ + i + 32];
                float2 s1h = *(const float2*)&sinp[t1 * DH_ + i + 32];
                float lo0 = acc[mi][ni][0],   lo1 = acc[mi][ni][1];
                float lo2 = acc[mi][ni][2],   lo3 = acc[mi][ni][3];
                float hi0 = acc[mi][ni+4][0], hi1 = acc[mi][ni+4][1];
                float hi2 = acc[mi][ni+4][2], hi3 = acc[mi][ni+4][3];
                // row r0 (elements 0,1), row r1 (elements 2,3)
                st_h2(dst + (size_t)r0 * D_ + cbase + i,
                      (lo0 * c0l.x - hi0 * s0l.x) * sc,
                      (lo1 * c0l.y - hi1 * s0l.y) * sc);
                st_h2(dst + (size_t)r0 * D_ + cbase + i + 32,
                      (hi0 * c0h.x + lo0 * s0h.x) * sc,
                      (hi1 * c0h.y + lo1 * s0h.y) * sc);
                st_h2(dst + (size_t)r1 * D_ + cbase + i,
                      (lo2 * c1l.x - hi2 * s1l.x) * sc,
                      (lo3 * c1l.y - hi3 * s1l.y) * sc);
                st_h2(dst + (size_t)r1 * D_ + cbase + i + 32,
                      (hi2 * c1h.x + lo2 * s1h.x) * sc,
                      (hi3 * c1h.y + lo3 * s1h.y) * sc);
            }
        }
    } else {
        // V: transpose 128x128 block through smem, store V^T [bh][dh][T] fp16
        __syncthreads();
        __half* tsm = hsm;                  // [128 cols][136] fp16 = 34816 B
        #pragma unroll
        for (int mi = 0; mi < 2; mi++) {
            int rl = warp_m * 32 + mi * 16 + grp;   // block-local rows rl, rl+8
            #pragma unroll
            for (int ni = 0; ni < 8; ni++) {
                int c = warp_n * 64 + ni * 8 + 2 * tq;
                tsm[(c)     * 136 + rl]     = __float2half_rn(acc[mi][ni][0]);
                tsm[(c + 1) * 136 + rl]     = __float2half_rn(acc[mi][ni][1]);
                tsm[(c)     * 136 + rl + 8] = __float2half_rn(acc[mi][ni][2]);
                tsm[(c + 1) * 136 + rl + 8] = __float2half_rn(acc[mi][ni][3]);
            }
        }
        __syncthreads();
        int b  = row0 >> 11;                 // batch
        int tb = row0 & (T_ - 1);            // token base
        int headbase = (col0 - 2048) >> 6;
        int c  = tid >> 1, hf = tid & 1;     // c: 0..127, hf: half of 128 tokens
        int hh = headbase + (c >> 6), d = c & 63;
        const uint4* src = (const uint4*)(tsm + c * 136 + hf * 64);
        uint4* dv = (uint4*)(Vh + (((size_t)(b * H_ + hh)) * DH_ + d) * T_ + tb + hf * 64);
        #pragma unroll
        for (int j = 0; j < 8; j++) dv[j] = src[j];
    }
}

// ---------------------------------------------------------------------------
// Plain fp16 GEMM (Wo projection): C fp32 = A @ B^T
// ---------------------------------------------------------------------------
__global__ __launch_bounds__(256) void gemm_h(const __half* __restrict__ A,
                                              const __half* __restrict__ Bw,
                                              float* __restrict__ C, int N)
{
    extern __shared__ __half hsm[];
    const int tid  = threadIdx.x;
    const int lane = tid & 31;
    const int warp = tid >> 5;
    const int warp_m = warp & 3;
    const int warp_n = warp >> 2;
    const int grp = lane >> 2;
    const int tq  = lane & 3;
    const int row0 = blockIdx.y * 128;
    const int col0 = blockIdx.x * 128;

    GEMM_MAINLOOP(A, Bw, D_)

    #pragma unroll
    for (int mi = 0; mi < 2; mi++) {
        int r = row0 + warp_m * 32 + mi * 16 + grp;
        #pragma unroll
        for (int ni = 0; ni < 8; ni++) {
            int c = col0 + warp_n * 64 + ni * 8 + tq * 2;
            *(float2*)&C[(size_t)r * N + c]       = make_float2(acc[mi][ni][0], acc[mi][ni][1]);
            *(float2*)&C[(size_t)(r + 8) * N + c] = make_float2(acc[mi][ni][2], acc[mi][ni][3]);
        }
    }
}

// ---------------------------------------------------------------------------
// fp16 tensor-core flash attention (causal, online softmax).
// ---------------------------------------------------------------------------
#define ASTRIDE 72
#define ATILE_H (64*ASTRIDE*2)     // fp16 per stage (K + V^T)

__global__ __launch_bounds__(256) void attn_h(const __half* __restrict__ Qh,
                                              const __half* __restrict__ Kh,
                                              const __half* __restrict__ Vh,
                                              __half* __restrict__ Oh)
{
    __shared__ __align__(16) __half hsm[2 * ATILE_H];   // 36864 B

    int b = blockIdx.z, h = blockIdx.y;
    int q0 = (gridDim.x - 1 - blockIdx.x) * 128;
    int tid = threadIdx.x;
    int lane = tid & 31, warp = tid >> 5;
    int grp = lane >> 2, tq = lane & 3;

    const __half* Qg = Qh + (size_t)b * T_ * D_ + h * DH_;
    const __half* Kg = Kh + (size_t)b * T_ * D_ + h * DH_;
    const __half* Vg = Vh + ((size_t)(b * H_ + h) * DH_) * T_;
    __half* Og = Oh + (size_t)b * T_ * D_ + h * DH_;

    const int qw  = q0 + 16 * warp;
    const int r0g = qw + grp;
    const int r1g = qw + grp + 8;

    uint32_t qa[4][4];
    #pragma unroll
    for (int ks = 0; ks < 4; ks++) {
        qa[ks][0] = ld32(Qg + (size_t)r0g * D_ + 16*ks + 2*tq);
        qa[ks][1] = ld32(Qg + (size_t)r1g * D_ + 16*ks + 2*tq);
        qa[ks][2] = ld32(Qg + (size_t)r0g * D_ + 16*ks + 2*tq + 8);
        qa[ks][3] = ld32(Qg + (size_t)r1g * D_ + 16*ks + 2*tq + 8);
    }

    float oacc[8][4];
    #pragma unroll
    for (int nb = 0; nb < 8; nb++)
        #pragma unroll
        for (int e = 0; e < 4; e++) oacc[nb][e] = 0.f;

    float m0 = -1e30f, m1 = -1e30f, l0 = 0.f, l1 = 0.f;

    auto load_tile = [&](int s, int j0) {
        __half* Ks = hsm + s * ATILE_H;
        __half* Vs = Ks + 64 * ASTRIDE;
        #pragma unroll
        for (int i = 0; i < 4; i++) {
            int idx = tid + i * 256;
            int mat = idx >> 9;
            int r   = (idx >> 3) & 63;
            int seg = idx & 7;
            if (mat == 0)
                cp16(Ks + r * ASTRIDE + seg * 8, Kg + (size_t)(j0 + r) * D_ + seg * 8);
            else
                cp16(Vs + r * ASTRIDE + seg * 8, Vg + (size_t)r * T_ + j0 + seg * 8);
        }
        CP_COMMIT();
    };

    const int nt = q0 / 64 + 2;
    load_tile(0, 0);

    for (int t = 0; t < nt; ++t) {
        if (t + 1 < nt) { load_tile((t + 1) & 1, (t + 1) * 64); CP_WAIT(1); }
        else            { CP_WAIT(0); }
        __syncthreads();

        const int j0 = t * 64;
        const __half* Ks = hsm + (t & 1) * ATILE_H;
        const __half* Vs = Ks + 64 * ASTRIDE;

        if (j0 <= qw + 15) {
            const bool full = (j0 + 63 <= qw);

            float p[8][4];
            #pragma unroll
            for (int nb = 0; nb < 8; nb++)
                #pragma unroll
                for (int e = 0; e < 4; e++) p[nb][e] = 0.f;

            #pragma unroll
            for (int ks = 0; ks < 4; ks++) {
                #pragma unroll
                for (int nb = 0; nb < 8; nb++) {
                    uint32_t b0 = ld32(Ks + (8*nb + grp) * ASTRIDE + 16*ks + 2*tq);
                    uint32_t b1 = ld32(Ks + (8*nb + grp) * ASTRIDE + 16*ks + 2*tq + 8);
                    mma_f16(p[nb], qa[ks][0], qa[ks][1], qa[ks][2], qa[ks][3], b0, b1);
                }
            }

            float mx0 = -1e30f, mx1 = -1e30f;
            #pragma unroll
            for (int nb = 0; nb < 8; nb++) {
                int c = j0 + 8*nb + 2*tq;
                if (!full) {
                    p[nb][0] = (c     <= r0g) ? p[nb][0] : -1e30f;
                    p[nb][1] = (c + 1 <= r0g) ? p[nb][1] : -1e30f;
                    p[nb][2] = (c     <= r1g) ? p[nb][2] : -1e30f;
                    p[nb][3] = (c + 1 <= r1g) ? p[nb][3] : -1e30f;
                }
                mx0 = fmaxf(mx0, fmaxf(p[nb][0], p[nb][1]));
                mx1 = fmaxf(mx1, fmaxf(p[nb][2], p[nb][3]));
            }
            mx0 = fmaxf(mx0, __shfl_xor_sync(0xffffffffu, mx0, 1));
            mx0 = fmaxf(mx0, __shfl_xor_sync(0xffffffffu, mx0, 2));
            mx1 = fmaxf(mx1, __shfl_xor_sync(0xffffffffu, mx1, 1));
            mx1 = fmaxf(mx1, __shfl_xor_sync(0xffffffffu, mx1, 2));

            float mn0 = fmaxf(m0, mx0), mn1 = fmaxf(m1, mx1);
            float cr0 = __expf(m0 - mn0), cr1 = __expf(m1 - mn1);
            m0 = mn0; m1 = mn1;
            l0 *= cr0; l1 *= cr1;
            #pragma unroll
            for (int nb = 0; nb < 8; nb++) {
                oacc[nb][0] *= cr0; oacc[nb][1] *= cr0;
                oacc[nb][2] *= cr1; oacc[nb][3] *= cr1;
            }

            uint32_t pa01[8], pa23[8];
            #pragma unroll
            for (int nb = 0; nb < 8; nb++) {
                float e0 = __expf(p[nb][0] - m0);
                float e1 = __expf(p[nb][1] - m0);
                float e2 = __expf(p[nb][2] - m1);
                float e3 = __expf(p[nb][3] - m1);
                __half2 h01 = __floats2half2_rn(e0, e1);
                __half2 h23 = __floats2half2_rn(e2, e3);
                float2 f01 = __half22float2(h01);
                float2 f23 = __half22float2(h23);
                l0 += f01.x + f01.y;
                l1 += f23.x + f23.y;
                pa01[nb] = *(uint32_t*)&h01;
                pa23[nb] = *(uint32_t*)&h23;
            }

            #pragma unroll
            for (int ks = 0; ks < 4; ks++) {
                uint32_t a0 = pa01[2*ks];
                uint32_t a1 = pa23[2*ks];
                uint32_t a2 = pa01[2*ks + 1];
                uint32_t a3 = pa23[2*ks + 1];
                #pragma unroll
                for (int nb = 0; nb < 8; nb++) {
                    uint32_t b0 = ld32(Vs + (8*nb + grp) * ASTRIDE + 16*ks + 2*tq);
                    uint32_t b1 = ld32(Vs + (8*nb + grp) * ASTRIDE + 16*ks + 2*tq + 8);
                    mma_f16(oacc[nb], a0, a1, a2, a3, b0, b1);
                }
            }
        }
        __syncthreads();
    }

    l0 += __shfl_xor_sync(0xffffffffu, l0, 1);
    l0 += __shfl_xor_sync(0xffffffffu, l0, 2);
    l1 += __shfl_xor_sync(0xffffffffu, l1, 1);
    l1 += __shfl_xor_sync(0xffffffffu, l1, 2);
    float inv0 = 1.f / l0, inv1 = 1.f / l1;

    #pragma unroll
    for (int nb = 0; nb < 8; nb++) {
        int c = 8*nb + 2*tq;
        st_h2(Og + (size_t)r0g * D_ + c, oacc[nb][0] * inv0, oacc[nb][1] * inv0);
        st_h2(Og + (size_t)r1g * D_ + c, oacc[nb][2] * inv1, oacc[nb][3] * inv1);
    }
}

// ---------------------------------------------------------------------------
extern "C" void kernel_launch(void* const* d_in, const int* in_sizes, int n_in,
                              void* d_out, int out_size)
{
    const float* x    = (const float*)d_in[0];
    const float* cosp = (const float*)d_in[1];
    const float* sinp = (const float*)d_in[2];
    const float* Wq   = (const float*)d_in[3];
    const float* Wk   = (const float*)d_in[4];
    const float* Wv   = (const float*)d_in[5];
    const float* Wo   = (const float*)d_in[6];
    float* out = (float*)d_out;

    __half *xh, *wqkvh, *woh, *qh, *kh, *vh, *ah;
    cudaGetSymbolAddress((void**)&xh,    g_xh);
    cudaGetSymbolAddress((void**)&wqkvh, g_wqkvh);
    cudaGetSymbolAddress((void**)&woh,   g_woh);
    cudaGetSymbolAddress((void**)&qh,    g_qh);
    cudaGetSymbolAddress((void**)&kh,    g_kh);
    cudaGetSymbolAddress((void**)&vh,    g_vh);
    cudaGetSymbolAddress((void**)&ah,    g_ah);

    cudaFuncSetAttribute(gemm_qkv, cudaFuncAttributeMaxDynamicSharedMemorySize, GSMEM);
    cudaFuncSetAttribute(gemm_h,   cudaFuncAttributeMaxDynamicSharedMemorySize, GSMEM);

    // Prep: convert x; transpose+convert weights
    int n4x = (int)(ELEMS_ / 4);
    cvt_h<<<(n4x + 255) / 256, 256>>>(x, xh, n4x);
    dim3 wthr(32, 8), wgrid(32, 32);
    packwT_h<<<wgrid, wthr>>>(Wq, wqkvh, 0);
    packwT_h<<<wgrid, wthr>>>(Wk, wqkvh, 1024);
    packwT_h<<<wgrid, wthr>>>(Wv, wqkvh, 2048);
    packwT_h<<<wgrid, wthr>>>(Wo, woh, 0);

    // Fused QKV projection + RoPE + fp16 convert + V transpose
    dim3 qgrid(QKVN_ / 128, ROWS_ / 128);   // (24, 64)
    gemm_qkv<<<qgrid, 256, GSMEM>>>(xh, wqkvh, qh, kh, vh, cosp, sinp);

    // Attention (fp16 HMMA)
    dim3 agrid(T_ / 128, H_, B_);
    attn_h<<<agrid, 256>>>(qh, kh, vh, ah);

    // Output projection (fp32 out)
    dim3 ogrid(D_ / 128, ROWS_ / 128);      // (8, 64)
    gemm_h<<<ogrid, 256, GSMEM>>>(ah, woh, out, D_);
}

// round 13
// speedup vs baseline: 1.5089x; 1.5089x over previous
#include <cuda_runtime.h>
#include <cuda_fp16.h>
#include <math.h>
#include <stdint.h>

// Problem constants
#define B_  4
#define T_  2048
#define D_  1024
#define H_  16
#define DH_ 64
#define ROWS_ (B_*T_)              // 8192
#define ELEMS_ ((size_t)ROWS_*D_)  // 8,388,608
#define QKVN_ 3072                 // fused QKV width

// Scratch (device globals — no allocation)
__device__ __half g_xh[ELEMS_];                    // fp16 x            [M][1024]
__device__ __half g_wqkvh[(size_t)QKVN_*D_];       // fp16 [Wq|Wk|Wv]^T [3072][1024]
__device__ __half g_woh[(size_t)D_*D_];            // fp16 Wo^T         [1024][1024]
__device__ __half g_qkvh[(size_t)ROWS_*QKVN_];     // fused QKV fp16    [M][3072]
__device__ __half g_qh[ELEMS_];                    // fp16 Q (roped, *1/8) [M][1024]
__device__ __half g_kh[ELEMS_];                    // fp16 K (roped)       [M][1024]
__device__ __half g_vh[ELEMS_];                    // fp16 V^T   [B*H][64 dh][2048 t]
__device__ __half g_ah[ELEMS_];                    // fp16 attn out     [M][1024]

// ---------------------------------------------------------------------------
// Helpers
// ---------------------------------------------------------------------------
__device__ __forceinline__ void mma_f16(float c[4],
                                        uint32_t a0, uint32_t a1, uint32_t a2, uint32_t a3,
                                        uint32_t b0, uint32_t b1)
{
    asm volatile(
        "mma.sync.aligned.m16n8k16.row.col.f32.f16.f16.f32 "
        "{%0,%1,%2,%3}, {%4,%5,%6,%7}, {%8,%9}, {%0,%1,%2,%3};"
        : "+f"(c[0]), "+f"(c[1]), "+f"(c[2]), "+f"(c[3])
        : "r"(a0), "r"(a1), "r"(a2), "r"(a3), "r"(b0), "r"(b1));
}
__device__ __forceinline__ void cp16(void* s, const void* g) {
    uint32_t sa = (uint32_t)__cvta_generic_to_shared(s);
    asm volatile("cp.async.cg.shared.global [%0], [%1], 16;" :: "r"(sa), "l"(g));
}
#define CP_COMMIT() asm volatile("cp.async.commit_group;")
#define CP_WAIT(n)  asm volatile("cp.async.wait_group %0;" :: "n"(n))
__device__ __forceinline__ uint32_t ld32(const __half* p) {
    return *reinterpret_cast<const uint32_t*>(p);
}
__device__ __forceinline__ void st_h2(__half* p, float a, float b) {
    __half2 h = __floats2half2_rn(a, b);
    *(uint32_t*)p = *(uint32_t*)&h;
}

// ---------------------------------------------------------------------------
// Prep kernels
// ---------------------------------------------------------------------------
__global__ __launch_bounds__(256) void cvt_h(const float* __restrict__ src,
                                             __half* __restrict__ dst, int n4)
{
    int i = blockIdx.x * 256 + threadIdx.x;
    if (i >= n4) return;
    float4 v = ((const float4*)src)[i];
    __half2 h0 = __floats2half2_rn(v.x, v.y);
    __half2 h1 = __floats2half2_rn(v.z, v.w);
    *(uint2*)&dst[(size_t)i * 4] = make_uint2(*(uint32_t*)&h0, *(uint32_t*)&h1);
}

// All 4 weights: W [k][n] fp32 -> dst[(off+n)][k] fp16 (transpose + convert).
// gridDim.z = 4 selects the weight.
__global__ void packw_all(const float* __restrict__ Wq, const float* __restrict__ Wk,
                          const float* __restrict__ Wv, const float* __restrict__ Wo,
                          __half* __restrict__ wqkv, __half* __restrict__ wo)
{
    __shared__ float t[32][33];
    int which = blockIdx.z;
    const float* W = (which == 0) ? Wq : (which == 1) ? Wk : (which == 2) ? Wv : Wo;
    __half* out    = (which == 3) ? wo : wqkv;
    int off        = (which == 3) ? 0 : which * 1024;

    int n0 = blockIdx.x * 32, k0 = blockIdx.y * 32;
    int tx = threadIdx.x, ty = threadIdx.y;   // 32 x 8
    #pragma unroll
    for (int i = 0; i < 4; i++)
        t[ty + 8*i][tx] = W[(size_t)(k0 + ty + 8*i) * D_ + n0 + tx];
    __syncthreads();
    #pragma unroll
    for (int i = 0; i < 4; i++) {
        int n = n0 + ty + 8*i;
        out[(size_t)(off + n) * D_ + k0 + tx] = __float2half_rn(t[tx][ty + 8*i]);
    }
}

// ---------------------------------------------------------------------------
// fp16 tensor-core GEMM: A[M,K] @ B^T (B as [N][K] fp16), fp32 accumulate.
// Block tile 128x128, BK=64, 256 threads (8 warps), warp tile 32x64.
// half_out=1: write fp16 (QKV intermediate); half_out=0: write fp32 (final).
// ---------------------------------------------------------------------------
#define GSTRIDE 72
#define GSTAGE_H (128*GSTRIDE*2)           // fp16 count per stage (A+B)
#define GSMEM (2 * GSTAGE_H * 2)           // bytes: 73728

__global__ __launch_bounds__(256) void gemm_h(const __half* __restrict__ A,
                                              const __half* __restrict__ Bw,
                                              void* __restrict__ Cv,
                                              int N, int half_out)
{
    extern __shared__ __half hsm[];

    const int tid  = threadIdx.x;
    const int lane = tid & 31;
    const int warp = tid >> 5;
    const int warp_m = warp & 3;
    const int warp_n = warp >> 2;
    const int grp = lane >> 2;
    const int tq  = lane & 3;

    const int row0 = blockIdx.y * 128;
    const int col0 = blockIdx.x * 128;
    const int K = D_;

    float acc[2][8][4];
    #pragma unroll
    for (int mi = 0; mi < 2; mi++)
        #pragma unroll
        for (int ni = 0; ni < 8; ni++)
            #pragma unroll
            for (int e = 0; e < 4; e++) acc[mi][ni][e] = 0.f;

    auto load_stage = [&](int s, int k0) {
        __half* As = hsm + s * GSTAGE_H;
        __half* Bs = As + 128 * GSTRIDE;
        const __half* Ag = A + (size_t)row0 * K + k0;
        const __half* Bg = Bw + (size_t)col0 * K + k0;
        #pragma unroll
        for (int i = 0; i < 4; i++) {
            int idx = tid + i * 256;
            int r = idx >> 3, seg = idx & 7;
            cp16(As + r * GSTRIDE + seg * 8, Ag + (size_t)r * K + seg * 8);
            cp16(Bs + r * GSTRIDE + seg * 8, Bg + (size_t)r * K + seg * 8);
        }
        CP_COMMIT();
    };

    const int NIT = K >> 6;   // K/64
    load_stage(0, 0);

    for (int it = 0; it < NIT; ++it) {
        if (it + 1 < NIT) { load_stage((it + 1) & 1, (it + 1) << 6); CP_WAIT(1); }
        else              { CP_WAIT(0); }
        __syncthreads();

        const __half* As = hsm + (it & 1) * GSTAGE_H;
        const __half* Bs = As + 128 * GSTRIDE;

        #pragma unroll
        for (int ks = 0; ks < 4; ks++) {
            const int kk = 16 * ks;
            uint32_t bf[8][2];
            #pragma unroll
            for (int ni = 0; ni < 8; ni++) {
                int cb = warp_n * 64 + ni * 8 + grp;
                bf[ni][0] = ld32(Bs + cb * GSTRIDE + kk + 2*tq);
                bf[ni][1] = ld32(Bs + cb * GSTRIDE + kk + 2*tq + 8);
            }
            #pragma unroll
            for (int mi = 0; mi < 2; mi++) {
                int rb = warp_m * 32 + mi * 16;
                uint32_t a0 = ld32(As + (rb + grp)     * GSTRIDE + kk + 2*tq);
                uint32_t a1 = ld32(As + (rb + grp + 8) * GSTRIDE + kk + 2*tq);
                uint32_t a2 = ld32(As + (rb + grp)     * GSTRIDE + kk + 2*tq + 8);
                uint32_t a3 = ld32(As + (rb + grp + 8) * GSTRIDE + kk + 2*tq + 8);
                #pragma unroll
                for (int ni = 0; ni < 8; ni++)
                    mma_f16(acc[mi][ni], a0, a1, a2, a3, bf[ni][0], bf[ni][1]);
            }
        }
        __syncthreads();
    }

    if (half_out) {
        __half* C = (__half*)Cv;
        #pragma unroll
        for (int mi = 0; mi < 2; mi++) {
            int r = row0 + warp_m * 32 + mi * 16 + grp;
            #pragma unroll
            for (int ni = 0; ni < 8; ni++) {
                int c = col0 + warp_n * 64 + ni * 8 + tq * 2;
                st_h2(C + (size_t)r * N + c,       acc[mi][ni][0], acc[mi][ni][1]);
                st_h2(C + (size_t)(r + 8) * N + c, acc[mi][ni][2], acc[mi][ni][3]);
            }
        }
    } else {
        float* C = (float*)Cv;
        #pragma unroll
        for (int mi = 0; mi < 2; mi++) {
            int r = row0 + warp_m * 32 + mi * 16 + grp;
            #pragma unroll
            for (int ni = 0; ni < 8; ni++) {
                int c = col0 + warp_n * 64 + ni * 8 + tq * 2;
                *(float2*)&C[(size_t)r * N + c]       = make_float2(acc[mi][ni][0], acc[mi][ni][1]);
                *(float2*)&C[(size_t)(r + 8) * N + c] = make_float2(acc[mi][ni][2], acc[mi][ni][3]);
            }
        }
    }
}

// ---------------------------------------------------------------------------
// RoPE + scale: reads fused QKV fp16, writes Q (*1/8) and K fp16. half2 paths.
// ---------------------------------------------------------------------------
__global__ __launch_bounds__(256) void rope_h(const __half* __restrict__ QKV,
                                              __half* __restrict__ Qh,
                                              __half* __restrict__ Kh,
                                              const float* __restrict__ cosp,
                                              const float* __restrict__ sinp)
{
    int idx = blockIdx.x * blockDim.x + threadIdx.x;   // over ROWS_*H_*16
    if (idx >= ROWS_ * H_ * 16) return;
    int i = (idx & 15) * 2;             // 0..30
    int row = idx >> 4;                 // m*16 + h
    int m = row >> 4, h = row & 15;
    int t = m & (T_ - 1);
    float2 cl = *(const float2*)&cosp[t * DH_ + i];
    float2 sl = *(const float2*)&sinp[t * DH_ + i];
    float2 ch = *(const float2*)&cosp[t * DH_ + i + 32];
    float2 sh = *(const float2*)&sinp[t * DH_ + i + 32];
    size_t qb = (size_t)m * QKVN_ + h * DH_;
    size_t ob = (size_t)m * D_ + h * DH_;

    __half2 qlo = *(const __half2*)&QKV[qb + i];
    __half2 qhi = *(const __half2*)&QKV[qb + i + 32];
    float2 ql = __half22float2(qlo), qh2 = __half22float2(qhi);
    st_h2(Qh + ob + i,      (ql.x * cl.x - qh2.x * sl.x) * 0.125f,
                            (ql.y * cl.y - qh2.y * sl.y) * 0.125f);
    st_h2(Qh + ob + i + 32, (qh2.x * ch.x + ql.x * sh.x) * 0.125f,
                            (qh2.y * ch.y + ql.y * sh.y) * 0.125f);

    __half2 klo = *(const __half2*)&QKV[qb + 1024 + i];
    __half2 khi = *(const __half2*)&QKV[qb + 1024 + i + 32];
    float2 kl = __half22float2(klo), kh2 = __half22float2(khi);
    st_h2(Kh + ob + i,      kl.x * cl.x - kh2.x * sl.x,
                            kl.y * cl.y - kh2.y * sl.y);
    st_h2(Kh + ob + i + 32, kh2.x * ch.x + kl.x * sh.x,
                            kh2.y * ch.y + kl.y * sh.y);
}

// ---------------------------------------------------------------------------
// V transpose: QKV fp16 V-part [t][dh] -> Vh [bh][dh][T] fp16.
// Block (32,8), tile 32 tokens x 32 dh. Grid (T/32, 2, B*H).
// ---------------------------------------------------------------------------
__global__ void vtrans_h(const __half* __restrict__ QKV, __half* __restrict__ Vh)
{
    __shared__ __half t[32][33];
    int t0 = blockIdx.x * 32, d0 = blockIdx.y * 32;
    int bh = blockIdx.z;                    // b*16 + h
    int b = bh >> 4, h = bh & 15;
    int tx = threadIdx.x, ty = threadIdx.y;
    const __half* src = QKV + (size_t)b * T_ * QKVN_ + 2048 + h * DH_;
    #pragma unroll
    for (int i = 0; i < 4; i++)
        t[ty + 8*i][tx] = src[(size_t)(t0 + ty + 8*i) * QKVN_ + d0 + tx];
    __syncthreads();
    __half* dst = Vh + ((size_t)bh * DH_) * T_;
    #pragma unroll
    for (int i = 0; i < 4; i++) {
        int dh = d0 + ty + 8*i;
        dst[(size_t)dh * T_ + t0 + tx] = t[tx][ty + 8*i];
    }
}

// ---------------------------------------------------------------------------
// fp16 tensor-core flash attention (causal, online softmax).
// Block: 128 q-rows, 8 warps (16 q-rows each). Key tiles of 64, double-buffered.
// P C-frag -> A-frag is a pure half2 pack. Scale folded into Q.
// Block q-order reversed (heavy blocks first).
// ---------------------------------------------------------------------------
#define ASTRIDE 72
#define ATILE_H (64*ASTRIDE*2)     // fp16 per stage (K + V^T)

__global__ __launch_bounds__(256) void attn_h(const __half* __restrict__ Qh,
                                              const __half* __restrict__ Kh,
                                              const __half* __restrict__ Vh,
                                              __half* __restrict__ Oh)
{
    __shared__ __align__(16) __half hsm[2 * ATILE_H];   // 36864 B

    int b = blockIdx.z, h = blockIdx.y;
    int q0 = (gridDim.x - 1 - blockIdx.x) * 128;
    int tid = threadIdx.x;
    int lane = tid & 31, warp = tid >> 5;
    int grp = lane >> 2, tq = lane & 3;

    const __half* Qg = Qh + (size_t)b * T_ * D_ + h * DH_;
    const __half* Kg = Kh + (size_t)b * T_ * D_ + h * DH_;
    const __half* Vg = Vh + ((size_t)(b * H_ + h) * DH_) * T_;
    __half* Og = Oh + (size_t)b * T_ * D_ + h * DH_;

    const int qw  = q0 + 16 * warp;
    const int r0g = qw + grp;
    const int r1g = qw + grp + 8;

    uint32_t qa[4][4];
    #pragma unroll
    for (int ks = 0; ks < 4; ks++) {
        qa[ks][0] = ld32(Qg + (size_t)r0g * D_ + 16*ks + 2*tq);
        qa[ks][1] = ld32(Qg + (size_t)r1g * D_ + 16*ks + 2*tq);
        qa[ks][2] = ld32(Qg + (size_t)r0g * D_ + 16*ks + 2*tq + 8);
        qa[ks][3] = ld32(Qg + (size_t)r1g * D_ + 16*ks + 2*tq + 8);
    }

    float oacc[8][4];
    #pragma unroll
    for (int nb = 0; nb < 8; nb++)
        #pragma unroll
        for (int e = 0; e < 4; e++) oacc[nb][e] = 0.f;

    float m0 = -1e30f, m1 = -1e30f, l0 = 0.f, l1 = 0.f;

    auto load_tile = [&](int s, int j0) {
        __half* Ks = hsm + s * ATILE_H;
        __half* Vs = Ks + 64 * ASTRIDE;
        #pragma unroll
        for (int i = 0; i < 4; i++) {
            int idx = tid + i * 256;
            int mat = idx >> 9;
            int r   = (idx >> 3) & 63;
            int seg = idx & 7;
            if (mat == 0)
                cp16(Ks + r * ASTRIDE + seg * 8, Kg + (size_t)(j0 + r) * D_ + seg * 8);
            else
                cp16(Vs + r * ASTRIDE + seg * 8, Vg + (size_t)r * T_ + j0 + seg * 8);
        }
        CP_COMMIT();
    };

    const int nt = q0 / 64 + 2;
    load_tile(0, 0);

    for (int t = 0; t < nt; ++t) {
        if (t + 1 < nt) { load_tile((t + 1) & 1, (t + 1) * 64); CP_WAIT(1); }
        else            { CP_WAIT(0); }
        __syncthreads();

        const int j0 = t * 64;
        const __half* Ks = hsm + (t & 1) * ATILE_H;
        const __half* Vs = Ks + 64 * ASTRIDE;

        if (j0 <= qw + 15) {
            const bool full = (j0 + 63 <= qw);

            float p[8][4];
            #pragma unroll
            for (int nb = 0; nb < 8; nb++)
                #pragma unroll
                for (int e = 0; e < 4; e++) p[nb][e] = 0.f;

            #pragma unroll
            for (int ks = 0; ks < 4; ks++) {
                #pragma unroll
                for (int nb = 0; nb < 8; nb++) {
                    uint32_t b0 = ld32(Ks + (8*nb + grp) * ASTRIDE + 16*ks + 2*tq);
                    uint32_t b1 = ld32(Ks + (8*nb + grp) * ASTRIDE + 16*ks + 2*tq + 8);
                    mma_f16(p[nb], qa[ks][0], qa[ks][1], qa[ks][2], qa[ks][3], b0, b1);
                }
            }

            float mx0 = -1e30f, mx1 = -1e30f;
            #pragma unroll
            for (int nb = 0; nb < 8; nb++) {
                int c = j0 + 8*nb + 2*tq;
                if (!full) {
                    p[nb][0] = (c     <= r0g) ? p[nb][0] : -1e30f;
                    p[nb][1] = (c + 1 <= r0g) ? p[nb][1] : -1e30f;
                    p[nb][2] = (c     <= r1g) ? p[nb][2] : -1e30f;
                    p[nb][3] = (c + 1 <= r1g) ? p[nb][3] : -1e30f;
                }
                mx0 = fmaxf(mx0, fmaxf(p[nb][0], p[nb][1]));
                mx1 = fmaxf(mx1, fmaxf(p[nb][2], p[nb][3]));
            }
            mx0 = fmaxf(mx0, __shfl_xor_sync(0xffffffffu, mx0, 1));
            mx0 = fmaxf(mx0, __shfl_xor_sync(0xffffffffu, mx0, 2));
            mx1 = fmaxf(mx1, __shfl_xor_sync(0xffffffffu, mx1, 1));
            mx1 = fmaxf(mx1, __shfl_xor_sync(0xffffffffu, mx1, 2));

            float mn0 = fmaxf(m0, mx0), mn1 = fmaxf(m1, mx1);
            float cr0 = __expf(m0 - mn0), cr1 = __expf(m1 - mn1);
            m0 = mn0; m1 = mn1;
            l0 *= cr0; l1 *= cr1;
            #pragma unroll
            for (int nb = 0; nb < 8; nb++) {
                oacc[nb][0] *= cr0; oacc[nb][1] *= cr0;
                oacc[nb][2] *= cr1; oacc[nb][3] *= cr1;
            }

            uint32_t pa01[8], pa23[8];
            #pragma unroll
            for (int nb = 0; nb < 8; nb++) {
                float e0 = __expf(p[nb][0] - m0);
                float e1 = __expf(p[nb][1] - m0);
                float e2 = __expf(p[nb][2] - m1);
                float e3 = __expf(p[nb][3] - m1);
                __half2 h01 = __floats2half2_rn(e0, e1);
                __half2 h23 = __floats2half2_rn(e2, e3);
                float2 f01 = __half22float2(h01);
                float2 f23 = __half22float2(h23);
                l0 += f01.x + f01.y;
                l1 += f23.x + f23.y;
                pa01[nb] = *(uint32_t*)&h01;
                pa23[nb] = *(uint32_t*)&h23;
            }

            #pragma unroll
            for (int ks = 0; ks < 4; ks++) {
                uint32_t a0 = pa01[2*ks];
                uint32_t a1 = pa23[2*ks];
                uint32_t a2 = pa01[2*ks + 1];
                uint32_t a3 = pa23[2*ks + 1];
                #pragma unroll
                for (int nb = 0; nb < 8; nb++) {
                    uint32_t b0 = ld32(Vs + (8*nb + grp) * ASTRIDE + 16*ks + 2*tq);
                    uint32_t b1 = ld32(Vs + (8*nb + grp) * ASTRIDE + 16*ks + 2*tq + 8);
                    mma_f16(oacc[nb], a0, a1, a2, a3, b0, b1);
                }
            }
        }
        __syncthreads();
    }

    l0 += __shfl_xor_sync(0xffffffffu, l0, 1);
    l0 += __shfl_xor_sync(0xffffffffu, l0, 2);
    l1 += __shfl_xor_sync(0xffffffffu, l1, 1);
    l1 += __shfl_xor_sync(0xffffffffu, l1, 2);
    float inv0 = 1.f / l0, inv1 = 1.f / l1;

    #pragma unroll
    for (int nb = 0; nb < 8; nb++) {
        int c = 8*nb + 2*tq;
        st_h2(Og + (size_t)r0g * D_ + c, oacc[nb][0] * inv0, oacc[nb][1] * inv0);
        st_h2(Og + (size_t)r1g * D_ + c, oacc[nb][2] * inv1, oacc[nb][3] * inv1);
    }
}

// ---------------------------------------------------------------------------
extern "C" void kernel_launch(void* const* d_in, const int* in_sizes, int n_in,
                              void* d_out, int out_size)
{
    const float* x    = (const float*)d_in[0];
    const float* cosp = (const float*)d_in[1];
    const float* sinp = (const float*)d_in[2];
    const float* Wq   = (const float*)d_in[3];
    const float* Wk   = (const float*)d_in[4];
    const float* Wv   = (const float*)d_in[5];
    const float* Wo   = (const float*)d_in[6];
    float* out = (float*)d_out;

    __half *xh, *wqkvh, *woh, *qkvh, *qh, *kh, *vh, *ah;
    cudaGetSymbolAddress((void**)&xh,    g_xh);
    cudaGetSymbolAddress((void**)&wqkvh, g_wqkvh);
    cudaGetSymbolAddress((void**)&woh,   g_woh);
    cudaGetSymbolAddress((void**)&qkvh,  g_qkvh);
    cudaGetSymbolAddress((void**)&qh,    g_qh);
    cudaGetSymbolAddress((void**)&kh,    g_kh);
    cudaGetSymbolAddress((void**)&vh,    g_vh);
    cudaGetSymbolAddress((void**)&ah,    g_ah);

    cudaFuncSetAttribute(gemm_h, cudaFuncAttributeMaxDynamicSharedMemorySize, GSMEM);

    // Prep: convert x; transpose+convert all 4 weights in one launch
    int n4x = (int)(ELEMS_ / 4);
    cvt_h<<<(n4x + 255) / 256, 256>>>(x, xh, n4x);
    dim3 wthr(32, 8), wgrid(32, 32, 4);
    packw_all<<<wgrid, wthr>>>(Wq, Wk, Wv, Wo, wqkvh, woh);

    // Fused QKV projection (fp16 out)
    dim3 qgrid(QKVN_ / 128, ROWS_ / 128);   // (24, 64)
    gemm_h<<<qgrid, 256, GSMEM>>>(xh, wqkvh, qkvh, QKVN_, 1);

    // RoPE + scale (fp16 in/out); V transpose
    int rope_total = ROWS_ * H_ * 16;
    rope_h<<<(rope_total + 255) / 256, 256>>>(qkvh, qh, kh, cosp, sinp);
    dim3 vthr(32, 8), vgrid(T_ / 32, 2, B_ * H_);
    vtrans_h<<<vgrid, vthr>>>(qkvh, vh);

    // Attention (fp16 HMMA)
    dim3 agrid(T_ / 128, H_, B_);
    attn_h<<<agrid, 256>>>(qh, kh, vh, ah);

    // Output projection (fp32 out)
    dim3 ogrid(D_ / 128, ROWS_ / 128);      // (8, 64)
    gemm_h<<<ogrid, 256, GSMEM>>>(ah, woh, out, D_, 0);
}

// round 14
// speedup vs baseline: 1.5263x; 1.0116x over previous
#include <cuda_runtime.h>
#include <cuda_fp16.h>
#include <math.h>
#include <stdint.h>

// Problem constants
#define B_  4
#define T_  2048
#define D_  1024
#define H_  16
#define DH_ 64
#define ROWS_ (B_*T_)              // 8192
#define ELEMS_ ((size_t)ROWS_*D_)  // 8,388,608
#define QKVN_ 3072                 // fused QKV width

// Scratch (device globals — no allocation)
__device__ __half g_xh[ELEMS_];                    // fp16 x            [M][1024]
__device__ __half g_wqkvh[(size_t)QKVN_*D_];       // fp16 [Wq|Wk|Wv]^T [3072][1024]
__device__ __half g_woh[(size_t)D_*D_];            // fp16 Wo^T         [1024][1024]
__device__ __half g_qkvh[(size_t)ROWS_*QKVN_];     // fused QKV fp16    [M][3072]
__device__ __half g_qh[ELEMS_];                    // fp16 Q (roped, *log2e/8) [M][1024]
__device__ __half g_kh[ELEMS_];                    // fp16 K (roped)       [M][1024]
__device__ __half g_vh[ELEMS_];                    // fp16 V^T   [B*H][64 dh][2048 t]
__device__ __half g_ah[ELEMS_];                    // fp16 attn out     [M][1024]

#define QSCALE 0.18033688011112042f   // 0.125 * log2(e) — softmax runs in base-2

// ---------------------------------------------------------------------------
// Helpers
// ---------------------------------------------------------------------------
__device__ __forceinline__ void mma_f16(float c[4],
                                        uint32_t a0, uint32_t a1, uint32_t a2, uint32_t a3,
                                        uint32_t b0, uint32_t b1)
{
    asm volatile(
        "mma.sync.aligned.m16n8k16.row.col.f32.f16.f16.f32 "
        "{%0,%1,%2,%3}, {%4,%5,%6,%7}, {%8,%9}, {%0,%1,%2,%3};"
        : "+f"(c[0]), "+f"(c[1]), "+f"(c[2]), "+f"(c[3])
        : "r"(a0), "r"(a1), "r"(a2), "r"(a3), "r"(b0), "r"(b1));
}
__device__ __forceinline__ void cp16(void* s, const void* g) {
    uint32_t sa = (uint32_t)__cvta_generic_to_shared(s);
    asm volatile("cp.async.cg.shared.global [%0], [%1], 16;" :: "r"(sa), "l"(g));
}
#define CP_COMMIT() asm volatile("cp.async.commit_group;")
#define CP_WAIT(n)  asm volatile("cp.async.wait_group %0;" :: "n"(n))
__device__ __forceinline__ uint32_t ld32(const __half* p) {
    return *reinterpret_cast<const uint32_t*>(p);
}
__device__ __forceinline__ void st_h2(__half* p, float a, float b) {
    __half2 h = __floats2half2_rn(a, b);
    *(uint32_t*)p = *(uint32_t*)&h;
}
__device__ __forceinline__ float ex2(float x) {
    float r;
    asm("ex2.approx.f32 %0, %1;" : "=f"(r) : "f"(x));
    return r;
}

// ---------------------------------------------------------------------------
// Prep kernels
// ---------------------------------------------------------------------------
__global__ __launch_bounds__(256) void cvt_h(const float* __restrict__ src,
                                             __half* __restrict__ dst, int n4)
{
    int i = blockIdx.x * 256 + threadIdx.x;
    if (i >= n4) return;
    float4 v = ((const float4*)src)[i];
    __half2 h0 = __floats2half2_rn(v.x, v.y);
    __half2 h1 = __floats2half2_rn(v.z, v.w);
    *(uint2*)&dst[(size_t)i * 4] = make_uint2(*(uint32_t*)&h0, *(uint32_t*)&h1);
}

// All 4 weights: W [k][n] fp32 -> dst[(off+n)][k] fp16 (transpose + convert).
__global__ void packw_all(const float* __restrict__ Wq, const float* __restrict__ Wk,
                          const float* __restrict__ Wv, const float* __restrict__ Wo,
                          __half* __restrict__ wqkv, __half* __restrict__ wo)
{
    __shared__ float t[32][33];
    int which = blockIdx.z;
    const float* W = (which == 0) ? Wq : (which == 1) ? Wk : (which == 2) ? Wv : Wo;
    __half* out    = (which == 3) ? wo : wqkv;
    int off        = (which == 3) ? 0 : which * 1024;

    int n0 = blockIdx.x * 32, k0 = blockIdx.y * 32;
    int tx = threadIdx.x, ty = threadIdx.y;   // 32 x 8
    #pragma unroll
    for (int i = 0; i < 4; i++)
        t[ty + 8*i][tx] = W[(size_t)(k0 + ty + 8*i) * D_ + n0 + tx];
    __syncthreads();
    #pragma unroll
    for (int i = 0; i < 4; i++) {
        int n = n0 + ty + 8*i;
        out[(size_t)(off + n) * D_ + k0 + tx] = __float2half_rn(t[tx][ty + 8*i]);
    }
}

// ---------------------------------------------------------------------------
// fp16 tensor-core GEMM: A[M,K] @ B^T (B as [N][K] fp16), fp32 accumulate.
// Block tile 128x128, BK=64, 256 threads, warp tile 32x64.
// 3-stage cp.async pipeline, ONE __syncthreads per iteration.
// half_out=1: fp16 epilogue; half_out=0: fp32.
// ---------------------------------------------------------------------------
#define GSTRIDE 72
#define GSTAGE_H (128*GSTRIDE*2)           // fp16 count per stage (A+B)
#define GSMEM (3 * GSTAGE_H * 2)           // bytes: 110592

__global__ __launch_bounds__(256) void gemm_h(const __half* __restrict__ A,
                                              const __half* __restrict__ Bw,
                                              void* __restrict__ Cv,
                                              int N, int half_out)
{
    extern __shared__ __half hsm[];

    const int tid  = threadIdx.x;
    const int lane = tid & 31;
    const int warp = tid >> 5;
    const int warp_m = warp & 3;
    const int warp_n = warp >> 2;
    const int grp = lane >> 2;
    const int tq  = lane & 3;

    const int row0 = blockIdx.y * 128;
    const int col0 = blockIdx.x * 128;
    const int K = D_;

    float acc[2][8][4];
    #pragma unroll
    for (int mi = 0; mi < 2; mi++)
        #pragma unroll
        for (int ni = 0; ni < 8; ni++)
            #pragma unroll
            for (int e = 0; e < 4; e++) acc[mi][ni][e] = 0.f;

    auto load_stage = [&](int s, int chunk) {
        __half* As = hsm + s * GSTAGE_H;
        __half* Bs = As + 128 * GSTRIDE;
        const __half* Ag = A + (size_t)row0 * K + (chunk << 6);
        const __half* Bg = Bw + (size_t)col0 * K + (chunk << 6);
        #pragma unroll
        for (int i = 0; i < 4; i++) {
            int idx = tid + i * 256;
            int r = idx >> 3, seg = idx & 7;
            cp16(As + r * GSTRIDE + seg * 8, Ag + (size_t)r * K + seg * 8);
            cp16(Bs + r * GSTRIDE + seg * 8, Bg + (size_t)r * K + seg * 8);
        }
        CP_COMMIT();
    };

    const int NIT = K >> 6;   // 16
    load_stage(0, 0);
    load_stage(1, 1);

    #pragma unroll 1
    for (int it = 0; it < NIT; ++it) {
        if (it + 1 < NIT) { CP_WAIT(1); } else { CP_WAIT(0); }
        __syncthreads();
        if (it + 2 < NIT) load_stage((it + 2) % 3, it + 2);

        const __half* As = hsm + (it % 3) * GSTAGE_H;
        const __half* Bs = As + 128 * GSTRIDE;

        #pragma unroll
        for (int ks = 0; ks < 4; ks++) {
            const int kk = 16 * ks;
            uint32_t bf[8][2];
            #pragma unroll
            for (int ni = 0; ni < 8; ni++) {
                int cb = warp_n * 64 + ni * 8 + grp;
                bf[ni][0] = ld32(Bs + cb * GSTRIDE + kk + 2*tq);
                bf[ni][1] = ld32(Bs + cb * GSTRIDE + kk + 2*tq + 8);
            }
            #pragma unroll
            for (int mi = 0; mi < 2; mi++) {
                int rb = warp_m * 32 + mi * 16;
                uint32_t a0 = ld32(As + (rb + grp)     * GSTRIDE + kk + 2*tq);
                uint32_t a1 = ld32(As + (rb + grp + 8) * GSTRIDE + kk + 2*tq);
                uint32_t a2 = ld32(As + (rb + grp)     * GSTRIDE + kk + 2*tq + 8);
                uint32_t a3 = ld32(As + (rb + grp + 8) * GSTRIDE + kk + 2*tq + 8);
                #pragma unroll
                for (int ni = 0; ni < 8; ni++)
                    mma_f16(acc[mi][ni], a0, a1, a2, a3, bf[ni][0], bf[ni][1]);
            }
        }
    }

    if (half_out) {
        __half* C = (__half*)Cv;
        #pragma unroll
        for (int mi = 0; mi < 2; mi++) {
            int r = row0 + warp_m * 32 + mi * 16 + grp;
            #pragma unroll
            for (int ni = 0; ni < 8; ni++) {
                int c = col0 + warp_n * 64 + ni * 8 + tq * 2;
                st_h2(C + (size_t)r * N + c,       acc[mi][ni][0], acc[mi][ni][1]);
                st_h2(C + (size_t)(r + 8) * N + c, acc[mi][ni][2], acc[mi][ni][3]);
            }
        }
    } else {
        float* C = (float*)Cv;
        #pragma unroll
        for (int mi = 0; mi < 2; mi++) {
            int r = row0 + warp_m * 32 + mi * 16 + grp;
            #pragma unroll
            for (int ni = 0; ni < 8; ni++) {
                int c = col0 + warp_n * 64 + ni * 8 + tq * 2;
                *(float2*)&C[(size_t)r * N + c]       = make_float2(acc[mi][ni][0], acc[mi][ni][1]);
                *(float2*)&C[(size_t)(r + 8) * N + c] = make_float2(acc[mi][ni][2], acc[mi][ni][3]);
            }
        }
    }
}

// ---------------------------------------------------------------------------
// Fused RoPE (Q*log2e/8, K) + V transpose. Grid x: [0,8192) rope, [8192,16384) vtrans.
// ---------------------------------------------------------------------------
__global__ __launch_bounds__(256) void rope_vtrans(const __half* __restrict__ QKV,
                                                   __half* __restrict__ Qh,
                                                   __half* __restrict__ Kh,
                                                   __half* __restrict__ Vh,
                                                   const float* __restrict__ cosp,
                                                   const float* __restrict__ sinp)
{
    if (blockIdx.x < 8192) {
        int idx = blockIdx.x * 256 + threadIdx.x;   // over ROWS_*H_*16
        int i = (idx & 15) * 2;
        int row = idx >> 4;                 // m*16 + h
        int m = row >> 4, h = row & 15;
        int t = m & (T_ - 1);
        float2 cl = *(const float2*)&cosp[t * DH_ + i];
        float2 sl = *(const float2*)&sinp[t * DH_ + i];
        float2 ch = *(const float2*)&cosp[t * DH_ + i + 32];
        float2 sh = *(const float2*)&sinp[t * DH_ + i + 32];
        size_t qb = (size_t)m * QKVN_ + h * DH_;
        size_t ob = (size_t)m * D_ + h * DH_;

        __half2 qlo = *(const __half2*)&QKV[qb + i];
        __half2 qhi = *(const __half2*)&QKV[qb + i + 32];
        float2 ql = __half22float2(qlo), qh2 = __half22float2(qhi);
        st_h2(Qh + ob + i,      (ql.x * cl.x - qh2.x * sl.x) * QSCALE,
                                (ql.y * cl.y - qh2.y * sl.y) * QSCALE);
        st_h2(Qh + ob + i + 32, (qh2.x * ch.x + ql.x * sh.x) * QSCALE,
                                (qh2.y * ch.y + ql.y * sh.y) * QSCALE);

        __half2 klo = *(const __half2*)&QKV[qb + 1024 + i];
        __half2 khi = *(const __half2*)&QKV[qb + 1024 + i + 32];
        float2 kl = __half22float2(klo), kh2 = __half22float2(khi);
        st_h2(Kh + ob + i,      kl.x * cl.x - kh2.x * sl.x,
                                kl.y * cl.y - kh2.y * sl.y);
        st_h2(Kh + ob + i + 32, kh2.x * ch.x + kl.x * sh.x,
                                kh2.y * ch.y + kl.y * sh.y);
    } else {
        __shared__ __half t[32][33];
        int i = blockIdx.x - 8192;          // 64 * 2 * 64 blocks
        int t0 = (i & 63) * 32;
        int d0 = ((i >> 6) & 1) * 32;
        int bh = i >> 7;                    // b*16 + h
        int b = bh >> 4, h = bh & 15;
        int tx = threadIdx.x & 31, ty = threadIdx.x >> 5;   // 32 x 8
        const __half* src = QKV + (size_t)b * T_ * QKVN_ + 2048 + h * DH_;
        #pragma unroll
        for (int j = 0; j < 4; j++)
            t[ty + 8*j][tx] = src[(size_t)(t0 + ty + 8*j) * QKVN_ + d0 + tx];
        __syncthreads();
        __half* dst = Vh + ((size_t)bh * DH_) * T_;
        #pragma unroll
        for (int j = 0; j < 4; j++) {
            int dh = d0 + ty + 8*j;
            dst[(size_t)dh * T_ + t0 + tx] = t[tx][ty + 8*j];
        }
    }
}

// ---------------------------------------------------------------------------
// fp16 tensor-core flash attention (causal, online softmax in base-2).
// 3-stage cp.async pipeline, one __syncthreads per tile.
// ---------------------------------------------------------------------------
#define ASTRIDE 72
#define ATILE_H (64*ASTRIDE*2)     // fp16 per stage (K + V^T)

__global__ __launch_bounds__(256) void attn_h(const __half* __restrict__ Qh,
                                              const __half* __restrict__ Kh,
                                              const __half* __restrict__ Vh,
                                              __half* __restrict__ Oh)
{
    __shared__ __align__(16) __half hsm[3 * ATILE_H];   // 55296 B

    int b = blockIdx.z, h = blockIdx.y;
    int q0 = (gridDim.x - 1 - blockIdx.x) * 128;
    int tid = threadIdx.x;
    int lane = tid & 31, warp = tid >> 5;
    int grp = lane >> 2, tq = lane & 3;

    const __half* Qg = Qh + (size_t)b * T_ * D_ + h * DH_;
    const __half* Kg = Kh + (size_t)b * T_ * D_ + h * DH_;
    const __half* Vg = Vh + ((size_t)(b * H_ + h) * DH_) * T_;
    __half* Og = Oh + (size_t)b * T_ * D_ + h * DH_;

    const int qw  = q0 + 16 * warp;
    const int r0g = qw + grp;
    const int r1g = qw + grp + 8;

    uint32_t qa[4][4];
    #pragma unroll
    for (int ks = 0; ks < 4; ks++) {
        qa[ks][0] = ld32(Qg + (size_t)r0g * D_ + 16*ks + 2*tq);
        qa[ks][1] = ld32(Qg + (size_t)r1g * D_ + 16*ks + 2*tq);
        qa[ks][2] = ld32(Qg + (size_t)r0g * D_ + 16*ks + 2*tq + 8);
        qa[ks][3] = ld32(Qg + (size_t)r1g * D_ + 16*ks + 2*tq + 8);
    }

    float oacc[8][4];
    #pragma unroll
    for (int nb = 0; nb < 8; nb++)
        #pragma unroll
        for (int e = 0; e < 4; e++) oacc[nb][e] = 0.f;

    float m0 = -1e30f, m1 = -1e30f, l0 = 0.f, l1 = 0.f;

    auto load_tile = [&](int s, int j0) {
        __half* Ks = hsm + s * ATILE_H;
        __half* Vs = Ks + 64 * ASTRIDE;
        #pragma unroll
        for (int i = 0; i < 4; i++) {
            int idx = tid + i * 256;
            int mat = idx >> 9;
            int r   = (idx >> 3) & 63;
            int seg = idx & 7;
            if (mat == 0)
                cp16(Ks + r * ASTRIDE + seg * 8, Kg + (size_t)(j0 + r) * D_ + seg * 8);
            else
                cp16(Vs + r * ASTRIDE + seg * 8, Vg + (size_t)r * T_ + j0 + seg * 8);
        }
        CP_COMMIT();
    };

    const int nt = q0 / 64 + 2;   // >= 2
    load_tile(0, 0);
    load_tile(1, 64);

    #pragma unroll 1
    for (int t = 0; t < nt; ++t) {
        if (t + 1 < nt) { CP_WAIT(1); } else { CP_WAIT(0); }
        __syncthreads();
        if (t + 2 < nt) load_tile((t + 2) % 3, (t + 2) * 64);

        const int j0 = t * 64;
        const __half* Ks = hsm + (t % 3) * ATILE_H;
        const __half* Vs = Ks + 64 * ASTRIDE;

        if (j0 <= qw + 15) {
            const bool full = (j0 + 63 <= qw);

            float p[8][4];
            #pragma unroll
            for (int nb = 0; nb < 8; nb++)
                #pragma unroll
                for (int e = 0; e < 4; e++) p[nb][e] = 0.f;

            #pragma unroll
            for (int ks = 0; ks < 4; ks++) {
                #pragma unroll
                for (int nb = 0; nb < 8; nb++) {
                    uint32_t b0 = ld32(Ks + (8*nb + grp) * ASTRIDE + 16*ks + 2*tq);
                    uint32_t b1 = ld32(Ks + (8*nb + grp) * ASTRIDE + 16*ks + 2*tq + 8);
                    mma_f16(p[nb], qa[ks][0], qa[ks][1], qa[ks][2], qa[ks][3], b0, b1);
                }
            }

            float mx0 = -1e30f, mx1 = -1e30f;
            #pragma unroll
            for (int nb = 0; nb < 8; nb++) {
                int c = j0 + 8*nb + 2*tq;
                if (!full) {
                    p[nb][0] = (c     <= r0g) ? p[nb][0] : -1e30f;
                    p[nb][1] = (c + 1 <= r0g) ? p[nb][1] : -1e30f;
                    p[nb][2] = (c     <= r1g) ? p[nb][2] : -1e30f;
                    p[nb][3] = (c + 1 <= r1g) ? p[nb][3] : -1e30f;
                }
                mx0 = fmaxf(mx0, fmaxf(p[nb][0], p[nb][1]));
                mx1 = fmaxf(mx1, fmaxf(p[nb][2], p[nb][3]));
            }
            mx0 = fmaxf(mx0, __shfl_xor_sync(0xffffffffu, mx0, 1));
            mx0 = fmaxf(mx0, __shfl_xor_sync(0xffffffffu, mx0, 2));
            mx1 = fmaxf(mx1, __shfl_xor_sync(0xffffffffu, mx1, 1));
            mx1 = fmaxf(mx1, __shfl_xor_sync(0xffffffffu, mx1, 2));

            float mn0 = fmaxf(m0, mx0), mn1 = fmaxf(m1, mx1);
            float cr0 = ex2(m0 - mn0), cr1 = ex2(m1 - mn1);
            m0 = mn0; m1 = mn1;
            l0 *= cr0; l1 *= cr1;
            #pragma unroll
            for (int nb = 0; nb < 8; nb++) {
                oacc[nb][0] *= cr0; oacc[nb][1] *= cr0;
                oacc[nb][2] *= cr1; oacc[nb][3] *= cr1;
            }

            uint32_t pa01[8], pa23[8];
            #pragma unroll
            for (int nb = 0; nb < 8; nb++) {
                float e0 = ex2(p[nb][0] - m0);
                float e1 = ex2(p[nb][1] - m0);
                float e2 = ex2(p[nb][2] - m1);
                float e3 = ex2(p[nb][3] - m1);
                __half2 h01 = __floats2half2_rn(e0, e1);
                __half2 h23 = __floats2half2_rn(e2, e3);
                float2 f01 = __half22float2(h01);
                float2 f23 = __half22float2(h23);
                l0 += f01.x + f01.y;
                l1 += f23.x + f23.y;
                pa01[nb] = *(uint32_t*)&h01;
                pa23[nb] = *(uint32_t*)&h23;
            }

            #pragma unroll
            for (int ks = 0; ks < 4; ks++) {
                uint32_t a0 = pa01[2*ks];
                uint32_t a1 = pa23[2*ks];
                uint32_t a2 = pa01[2*ks + 1];
                uint32_t a3 = pa23[2*ks + 1];
                #pragma unroll
                for (int nb = 0; nb < 8; nb++) {
                    uint32_t b0 = ld32(Vs + (8*nb + grp) * ASTRIDE + 16*ks + 2*tq);
                    uint32_t b1 = ld32(Vs + (8*nb + grp) * ASTRIDE + 16*ks + 2*tq + 8);
                    mma_f16(oacc[nb], a0, a1, a2, a3, b0, b1);
                }
            }
        }
    }

    l0 += __shfl_xor_sync(0xffffffffu, l0, 1);
    l0 += __shfl_xor_sync(0xffffffffu, l0, 2);
    l1 += __shfl_xor_sync(0xffffffffu, l1, 1);
    l1 += __shfl_xor_sync(0xffffffffu, l1, 2);
    float inv0 = 1.f / l0, inv1 = 1.f / l1;

    #pragma unroll
    for (int nb = 0; nb < 8; nb++) {
        int c = 8*nb + 2*tq;
        st_h2(Og + (size_t)r0g * D_ + c, oacc[nb][0] * inv0, oacc[nb][1] * inv0);
        st_h2(Og + (size_t)r1g * D_ + c, oacc[nb][2] * inv1, oacc[nb][3] * inv1);
    }
}

// ---------------------------------------------------------------------------
extern "C" void kernel_launch(void* const* d_in, const int* in_sizes, int n_in,
                              void* d_out, int out_size)
{
    const float* x    = (const float*)d_in[0];
    const float* cosp = (const float*)d_in[1];
    const float* sinp = (const float*)d_in[2];
    const float* Wq   = (const float*)d_in[3];
    const float* Wk   = (const float*)d_in[4];
    const float* Wv   = (const float*)d_in[5];
    const float* Wo   = (const float*)d_in[6];
    float* out = (float*)d_out;

    __half *xh, *wqkvh, *woh, *qkvh, *qh, *kh, *vh, *ah;
    cudaGetSymbolAddress((void**)&xh,    g_xh);
    cudaGetSymbolAddress((void**)&wqkvh, g_wqkvh);
    cudaGetSymbolAddress((void**)&woh,   g_woh);
    cudaGetSymbolAddress((void**)&qkvh,  g_qkvh);
    cudaGetSymbolAddress((void**)&qh,    g_qh);
    cudaGetSymbolAddress((void**)&kh,    g_kh);
    cudaGetSymbolAddress((void**)&vh,    g_vh);
    cudaGetSymbolAddress((void**)&ah,    g_ah);

    cudaFuncSetAttribute(gemm_h, cudaFuncAttributeMaxDynamicSharedMemorySize, GSMEM);

    // Prep: convert x; transpose+convert all 4 weights in one launch
    int n4x = (int)(ELEMS_ / 4);
    cvt_h<<<(n4x + 255) / 256, 256>>>(x, xh, n4x);
    dim3 wthr(32, 8), wgrid(32, 32, 4);
    packw_all<<<wgrid, wthr>>>(Wq, Wk, Wv, Wo, wqkvh, woh);

    // Fused QKV projection (fp16 out)
    dim3 qgrid(QKVN_ / 128, ROWS_ / 128);   // (24, 64)
    gemm_h<<<qgrid, 256, GSMEM>>>(xh, wqkvh, qkvh, QKVN_, 1);

    // Fused RoPE + V transpose (one launch)
    rope_vtrans<<<16384, 256>>>(qkvh, qh, kh, vh, cosp, sinp);

    // Attention (fp16 HMMA, base-2 softmax)
    dim3 agrid(T_ / 128, H_, B_);
    attn_h<<<agrid, 256>>>(qh, kh, vh, ah);

    // Output projection (fp32 out)
    dim3 ogrid(D_ / 128, ROWS_ / 128);      // (8, 64)
    gemm_h<<<ogrid, 256, GSMEM>>>(ah, woh, out, D_, 0);
}